// round 1
// baseline (speedup 1.0000x reference)
#include <cuda_runtime.h>

// Problem shape (fixed by dataset): 100000 nodes, 3.2M edges, 256 -> 32 -> 16x2
#define F0 256
#define F1 32
#define F2 16
#define MAXN 100000

// Scratch (allocation-free rule: __device__ globals)
__device__ __align__(16) float g_dinv[MAXN];
__device__ int   g_degcnt[MAXN];
__device__ __align__(16) float g_hx  [MAXN * F1];   // x @ W1
__device__ __align__(16) float g_h   [MAXN * F1];   // relu(layer-1 out)
__device__ __align__(16) float g_agg1[MAXN * F1];
__device__ __align__(16) float g_agg2[MAXN * F1];

// ---------------------------------------------------------------------------
__global__ void zero_kernel(int n) {
    int total = n * F1;
    for (int i = blockIdx.x * blockDim.x + threadIdx.x; i < total;
         i += gridDim.x * blockDim.x) {
        g_agg1[i] = 0.0f;
        g_agg2[i] = 0.0f;
        if (i < n) g_degcnt[i] = 0;
    }
}

// in-degree count over dst = edge_index[1]
__global__ void deg_kernel(const int* __restrict__ ei, int E) {
    int e = blockIdx.x * blockDim.x + threadIdx.x;
    if (e < E) atomicAdd(&g_degcnt[ei[E + e]], 1);
}

__global__ void dinv_kernel(int n) {
    int i = blockIdx.x * blockDim.x + threadIdx.x;
    if (i < n) g_dinv[i] = rsqrtf((float)g_degcnt[i] + 1.0f);
}

// hx = x @ W1  (N x 256  @  256 x 32)
// block = 256 threads = 8 rows x 32 cols; W1 staged in smem (32 KB)
__global__ void gemm1_kernel(const float* __restrict__ x,
                             const float* __restrict__ W1, int n) {
    __shared__ float Ws[F0 * F1];
    for (int i = threadIdx.x; i < F0 * F1; i += blockDim.x) Ws[i] = W1[i];
    __syncthreads();
    int c = threadIdx.x & 31;
    int r = threadIdx.x >> 5;              // 0..7
    int row = blockIdx.x * 8 + r;
    if (row >= n) return;
    const float* xr = x + (size_t)row * F0;
    float acc = 0.0f;
#pragma unroll 8
    for (int k = 0; k < F0; k++) acc = fmaf(xr[k], Ws[k * F1 + c], acc);
    g_hx[(size_t)row * F1 + c] = acc;
}

// Edge scatter: 8 threads/edge, float4 per thread, vector red to L2.
// phase 0: agg1 += hx[src] * dinv[src]*dinv[dst]
// phase 1: agg2 += h [src] * dinv[src]*dinv[dst]
__global__ void scatter_kernel(const int* __restrict__ ei, int E, int phase) {
    long long gid = (long long)blockIdx.x * blockDim.x + threadIdx.x;
    int e = (int)(gid >> 3);
    if (e >= E) return;
    int j = (int)(gid & 7);
    int src = __ldg(&ei[e]);
    int dst = __ldg(&ei[E + e]);
    float w = g_dinv[src] * g_dinv[dst];
    const float* feat = phase ? g_h : g_hx;
    float*       agg  = phase ? g_agg2 : g_agg1;
    float4 v = *reinterpret_cast<const float4*>(feat + (size_t)src * F1 + j * 4);
    float4 m;
    m.x = v.x * w; m.y = v.y * w; m.z = v.z * w; m.w = v.w * w;
    float* p = agg + (size_t)dst * F1 + j * 4;
    asm volatile("red.global.add.v4.f32 [%0], {%1,%2,%3,%4};"
                 :: "l"(p), "f"(m.x), "f"(m.y), "f"(m.z), "f"(m.w)
                 : "memory");
}

// h = relu(agg1 + hx * dinv^2 + b1)
__global__ void sl_relu_kernel(const float* __restrict__ b1, int n) {
    int idx = blockIdx.x * blockDim.x + threadIdx.x;
    if (idx >= n * F1) return;
    int i = idx >> 5;
    int c = idx & 31;
    float d = g_dinv[i];
    float v = g_agg1[idx] + g_hx[idx] * d * d + b1[c];
    g_h[idx] = v > 0.0f ? v : 0.0f;
}

// tmp = agg2 + h*dinv^2 ; mu = tmp@Wm + bm ; sigma = tmp@Wv + bv
// block = 256 threads = 16 nodes x 16 cols
__global__ void final_kernel(const float* __restrict__ Wm,
                             const float* __restrict__ bm,
                             const float* __restrict__ Wv,
                             const float* __restrict__ bv,
                             float* __restrict__ out, int n) {
    __shared__ float Wms[F1 * F2];
    __shared__ float Wvs[F1 * F2];
    for (int i = threadIdx.x; i < F1 * F2; i += blockDim.x) {
        Wms[i] = Wm[i];
        Wvs[i] = Wv[i];
    }
    __syncthreads();
    int c = threadIdx.x & 15;
    int r = threadIdx.x >> 4;              // 0..15
    int node = blockIdx.x * 16 + r;
    if (node >= n) return;
    float d  = g_dinv[node];
    float d2 = d * d;
    float am = 0.0f, av = 0.0f;
#pragma unroll
    for (int k = 0; k < F1; k++) {
        float t = g_agg2[node * F1 + k] + g_h[node * F1 + k] * d2;
        am = fmaf(t, Wms[k * F2 + c], am);
        av = fmaf(t, Wvs[k * F2 + c], av);
    }
    out[(size_t)node * F2 + c]                    = am + bm[c];
    out[(size_t)n * F2 + (size_t)node * F2 + c]   = av + bv[c];
}

// ---------------------------------------------------------------------------
extern "C" void kernel_launch(void* const* d_in, const int* in_sizes, int n_in,
                              void* d_out, int out_size) {
    const float* x  = (const float*)d_in[0];
    const int*   ei = (const int*)  d_in[1];
    const float* W1 = (const float*)d_in[2];
    const float* b1 = (const float*)d_in[3];
    const float* Wm = (const float*)d_in[4];
    const float* bm = (const float*)d_in[5];
    const float* Wv = (const float*)d_in[6];
    const float* bv = (const float*)d_in[7];
    float* out = (float*)d_out;

    int n = in_sizes[0] / F0;      // 100000
    int E = in_sizes[1] / 2;       // 3200000

    int sblocks = (int)(((long long)E * 8 + 255) / 256);

    zero_kernel<<<2048, 256>>>(n);
    deg_kernel<<<(E + 255) / 256, 256>>>(ei, E);
    dinv_kernel<<<(n + 255) / 256, 256>>>(n);
    gemm1_kernel<<<(n + 7) / 8, 256>>>(x, W1, n);
    scatter_kernel<<<sblocks, 256>>>(ei, E, 0);
    sl_relu_kernel<<<(n * F1 + 255) / 256, 256>>>(b1, n);
    scatter_kernel<<<sblocks, 256>>>(ei, E, 1);
    final_kernel<<<(n + 15) / 16, 256>>>(Wm, bm, Wv, bv, out, n);
}

// round 2
// speedup vs baseline: 1.5064x; 1.5064x over previous
#include <cuda_runtime.h>

// Problem shape (fixed by dataset): 100000 nodes, 3.2M edges, 256 -> 32 -> 16x2
#define F0 256
#define F1 32
#define F2 16
#define MAXN 100000
#define KT 32            // K-tile for gemm1
#define GROWS 256        // rows per block in gemm1

// Scratch (allocation-free rule: __device__ globals)
__device__ __align__(16) float g_dinv[MAXN];
__device__ int   g_degcnt[MAXN];
__device__ __align__(16) float g_hx  [MAXN * F1];   // x @ W1
__device__ __align__(16) float g_h   [MAXN * F1];   // relu(layer-1 out)
__device__ __align__(16) float g_agg1[MAXN * F1];
__device__ __align__(16) float g_agg2[MAXN * F1];

// ---------------------------------------------------------------------------
__global__ void zero_kernel(int n) {
    int total = n * F1;
    for (int i = blockIdx.x * blockDim.x + threadIdx.x; i < total;
         i += gridDim.x * blockDim.x) {
        g_agg1[i] = 0.0f;
        g_agg2[i] = 0.0f;
        if (i < n) g_degcnt[i] = 0;
    }
}

// in-degree count over dst = edge_index[1]
__global__ void deg_kernel(const int* __restrict__ ei, int E) {
    int e = blockIdx.x * blockDim.x + threadIdx.x;
    if (e < E) atomicAdd(&g_degcnt[ei[E + e]], 1);
}

__global__ void dinv_kernel(int n) {
    int i = blockIdx.x * blockDim.x + threadIdx.x;
    if (i < n) g_dinv[i] = rsqrtf((float)g_degcnt[i] + 1.0f);
}

// hx = x @ W1  (N x 256  @  256 x 32), register-tiled.
// Block: 256 threads -> 256 rows x 32 cols. Thread tile: 4 rows x 8 cols.
//   cg = tid & 3   -> output cols [8*cg, 8*cg+8)
//   rg = tid >> 2  -> output rows [4*rg, 4*rg+4) within block
// x staged per K-tile in smem with stride 33 (conflict-free scalar reads),
// W K-tile (32x32) staged per tile.
__global__ void __launch_bounds__(256) gemm1_kernel(
        const float* __restrict__ x, const float* __restrict__ W1, int n) {
    __shared__ float xs[GROWS * (KT + 1)];   // stride 33
    __shared__ float Wts[KT * F1];           // 32 x 32

    int tid = threadIdx.x;
    int cg = tid & 3;
    int rg = tid >> 2;
    int row0 = blockIdx.x * GROWS;

    float acc[4][8];
#pragma unroll
    for (int i = 0; i < 4; i++)
#pragma unroll
        for (int j = 0; j < 8; j++) acc[i][j] = 0.0f;

    for (int kt = 0; kt < F0; kt += KT) {
        __syncthreads();
        // stage W tile: 32x32 floats = 256 float4, one per thread
        {
            float4 w = *reinterpret_cast<const float4*>(W1 + (size_t)(kt) * F1 + tid * 4);
            *reinterpret_cast<float4*>(&Wts[tid * 4]) = w;  // stays row-major: Wts[k][c]
        }
        // stage x tile: GROWS rows x KT cols. 2048 float4 loads, 8 per thread.
#pragma unroll
        for (int it = 0; it < 8; it++) {
            int i = tid + it * 256;
            int r = i >> 3;          // row within tile (KT/4 = 8 quads per row)
            int q = i & 7;
            int grow = row0 + r;
            float4 v = make_float4(0.f, 0.f, 0.f, 0.f);
            if (grow < n)
                v = *reinterpret_cast<const float4*>(x + (size_t)grow * F0 + kt + q * 4);
            float* dst = &xs[r * (KT + 1) + q * 4];
            dst[0] = v.x; dst[1] = v.y; dst[2] = v.z; dst[3] = v.w;
        }
        __syncthreads();

#pragma unroll
        for (int k = 0; k < KT; k++) {
            float xv[4];
#pragma unroll
            for (int i = 0; i < 4; i++)
                xv[i] = xs[(rg * 4 + i) * (KT + 1) + k];
            float4 w0 = *reinterpret_cast<const float4*>(&Wts[k * F1 + cg * 8]);
            float4 w1 = *reinterpret_cast<const float4*>(&Wts[k * F1 + cg * 8 + 4]);
#pragma unroll
            for (int i = 0; i < 4; i++) {
                acc[i][0] = fmaf(xv[i], w0.x, acc[i][0]);
                acc[i][1] = fmaf(xv[i], w0.y, acc[i][1]);
                acc[i][2] = fmaf(xv[i], w0.z, acc[i][2]);
                acc[i][3] = fmaf(xv[i], w0.w, acc[i][3]);
                acc[i][4] = fmaf(xv[i], w1.x, acc[i][4]);
                acc[i][5] = fmaf(xv[i], w1.y, acc[i][5]);
                acc[i][6] = fmaf(xv[i], w1.z, acc[i][6]);
                acc[i][7] = fmaf(xv[i], w1.w, acc[i][7]);
            }
        }
    }

#pragma unroll
    for (int i = 0; i < 4; i++) {
        int row = row0 + rg * 4 + i;
        if (row < n) {
            float4 o0 = make_float4(acc[i][0], acc[i][1], acc[i][2], acc[i][3]);
            float4 o1 = make_float4(acc[i][4], acc[i][5], acc[i][6], acc[i][7]);
            float* dst = &g_hx[(size_t)row * F1 + cg * 8];
            *reinterpret_cast<float4*>(dst)     = o0;
            *reinterpret_cast<float4*>(dst + 4) = o1;
        }
    }
}

// Edge scatter: 8 threads/edge, float4 per thread, vector red to L2.
// phase 0: agg1 += hx[src] * dinv[src]*dinv[dst]
// phase 1: agg2 += h [src] * dinv[src]*dinv[dst]
__global__ void scatter_kernel(const int* __restrict__ ei, int E, int phase) {
    long long gid = (long long)blockIdx.x * blockDim.x + threadIdx.x;
    int e = (int)(gid >> 3);
    if (e >= E) return;
    int j = (int)(gid & 7);
    int src = __ldg(&ei[e]);
    int dst = __ldg(&ei[E + e]);
    float w = g_dinv[src] * g_dinv[dst];
    const float* feat = phase ? g_h : g_hx;
    float*       agg  = phase ? g_agg2 : g_agg1;
    float4 v = *reinterpret_cast<const float4*>(feat + (size_t)src * F1 + j * 4);
    float4 m;
    m.x = v.x * w; m.y = v.y * w; m.z = v.z * w; m.w = v.w * w;
    float* p = agg + (size_t)dst * F1 + j * 4;
    asm volatile("red.global.add.v4.f32 [%0], {%1,%2,%3,%4};"
                 :: "l"(p), "f"(m.x), "f"(m.y), "f"(m.z), "f"(m.w)
                 : "memory");
}

// h = relu(agg1 + hx * dinv^2 + b1)
__global__ void sl_relu_kernel(const float* __restrict__ b1, int n) {
    int idx = blockIdx.x * blockDim.x + threadIdx.x;
    if (idx >= n * F1) return;
    int i = idx >> 5;
    int c = idx & 31;
    float d = g_dinv[i];
    float v = g_agg1[idx] + g_hx[idx] * d * d + b1[c];
    g_h[idx] = v > 0.0f ? v : 0.0f;
}

// tmp = agg2 + h*dinv^2 ; mu = tmp@Wm + bm ; sigma = tmp@Wv + bv
// block = 256 threads = 16 nodes x 16 cols
__global__ void final_kernel(const float* __restrict__ Wm,
                             const float* __restrict__ bm,
                             const float* __restrict__ Wv,
                             const float* __restrict__ bv,
                             float* __restrict__ out, int n) {
    __shared__ float Wms[F1 * F2];
    __shared__ float Wvs[F1 * F2];
    for (int i = threadIdx.x; i < F1 * F2; i += blockDim.x) {
        Wms[i] = Wm[i];
        Wvs[i] = Wv[i];
    }
    __syncthreads();
    int c = threadIdx.x & 15;
    int r = threadIdx.x >> 4;              // 0..15
    int node = blockIdx.x * 16 + r;
    if (node >= n) return;
    float d  = g_dinv[node];
    float d2 = d * d;
    float am = 0.0f, av = 0.0f;
#pragma unroll
    for (int k = 0; k < F1; k++) {
        float t = g_agg2[node * F1 + k] + g_h[node * F1 + k] * d2;
        am = fmaf(t, Wms[k * F2 + c], am);
        av = fmaf(t, Wvs[k * F2 + c], av);
    }
    out[(size_t)node * F2 + c]                    = am + bm[c];
    out[(size_t)n * F2 + (size_t)node * F2 + c]   = av + bv[c];
}

// ---------------------------------------------------------------------------
extern "C" void kernel_launch(void* const* d_in, const int* in_sizes, int n_in,
                              void* d_out, int out_size) {
    const float* x  = (const float*)d_in[0];
    const int*   ei = (const int*)  d_in[1];
    const float* W1 = (const float*)d_in[2];
    const float* b1 = (const float*)d_in[3];
    const float* Wm = (const float*)d_in[4];
    const float* bm = (const float*)d_in[5];
    const float* Wv = (const float*)d_in[6];
    const float* bv = (const float*)d_in[7];
    float* out = (float*)d_out;

    int n = in_sizes[0] / F0;      // 100000
    int E = in_sizes[1] / 2;       // 3200000

    int sblocks = (int)(((long long)E * 8 + 255) / 256);

    zero_kernel<<<2048, 256>>>(n);
    deg_kernel<<<(E + 255) / 256, 256>>>(ei, E);
    dinv_kernel<<<(n + 255) / 256, 256>>>(n);
    gemm1_kernel<<<(n + GROWS - 1) / GROWS, 256>>>(x, W1, n);
    scatter_kernel<<<sblocks, 256>>>(ei, E, 0);
    sl_relu_kernel<<<(n * F1 + 255) / 256, 256>>>(b1, n);
    scatter_kernel<<<sblocks, 256>>>(ei, E, 1);
    final_kernel<<<(n + 15) / 16, 256>>>(Wm, bm, Wv, bv, out, n);
}

// round 3
// speedup vs baseline: 1.8118x; 1.2027x over previous
#include <cuda_runtime.h>

// Problem shape (fixed by dataset): 100000 nodes, 3.2M edges, 256 -> 32 -> 16x2
#define F0 256
#define F1 32
#define F2 16
#define MAXN 100000
#define MAXE 3200000
#define KT 32            // K-tile for gemm1
#define GROWS 256        // rows per block in gemm1
#define SCAN_BLK 1024

// Scratch (allocation-free rule: __device__ globals)
__device__ __align__(16) float g_dinv[MAXN];
__device__ int    g_degcnt[MAXN];
__device__ int    g_off[MAXN + 1];
__device__ int    g_cursor[MAXN];
__device__ int    g_bsum[(MAXN + SCAN_BLK - 1) / SCAN_BLK];
__device__ __align__(16) float2 g_csr[MAXE];       // (src as int bits, weight)
__device__ __align__(16) float g_hx[MAXN * F1];    // x @ W1
__device__ __align__(16) float g_h [MAXN * F1];    // relu(layer-1 out)

// ---------------------------------------------------------------------------
__global__ void zero_kernel(int n) {
    int i = blockIdx.x * blockDim.x + threadIdx.x;
    if (i < n) g_degcnt[i] = 0;
}

// in-degree count over dst = edge_index[1]
__global__ void deg_kernel(const int* __restrict__ ei, int E) {
    int e = blockIdx.x * blockDim.x + threadIdx.x;
    if (e < E) atomicAdd(&g_degcnt[ei[E + e]], 1);
}

__global__ void dinv_kernel(int n) {
    int i = blockIdx.x * blockDim.x + threadIdx.x;
    if (i < n) g_dinv[i] = rsqrtf((float)g_degcnt[i] + 1.0f);
}

// ---- exclusive scan over degcnt -> g_off (3 kernels) ----------------------
__global__ void scan1_kernel(int n) {
    __shared__ int s[SCAN_BLK];
    int tid = threadIdx.x;
    int i = blockIdx.x * SCAN_BLK + tid;
    int v = (i < n) ? g_degcnt[i] : 0;
    s[tid] = v;
    __syncthreads();
    for (int off = 1; off < SCAN_BLK; off <<= 1) {
        int t = (tid >= off) ? s[tid - off] : 0;
        __syncthreads();
        if (tid >= off) s[tid] += t;
        __syncthreads();
    }
    if (i < n) g_off[i] = s[tid] - v;   // exclusive
    if (tid == SCAN_BLK - 1) g_bsum[blockIdx.x] = s[tid];
}

__global__ void scan2_kernel(int nb) {   // nb <= 128
    __shared__ int s[128];
    int tid = threadIdx.x;
    int v = (tid < nb) ? g_bsum[tid] : 0;
    s[tid] = v;
    __syncthreads();
    for (int off = 1; off < 128; off <<= 1) {
        int t = (tid >= off) ? s[tid - off] : 0;
        __syncthreads();
        if (tid >= off) s[tid] += t;
        __syncthreads();
    }
    if (tid < nb) g_bsum[tid] = s[tid] - v;  // exclusive
}

__global__ void scan3_kernel(int n, int E) {
    int i = blockIdx.x * blockDim.x + threadIdx.x;
    if (i < n) {
        int o = g_off[i] + g_bsum[i / SCAN_BLK];
        g_off[i] = o;
        g_cursor[i] = o;
    }
    if (i == 0) g_off[n] = E;
}

// ---- CSR fill: bucket edges by dst, record (src, dinv[src]*dinv[dst]) -----
__global__ void fill_kernel(const int* __restrict__ ei, int E) {
    int e = blockIdx.x * blockDim.x + threadIdx.x;
    if (e >= E) return;
    int src = ei[e];
    int dst = ei[E + e];
    int pos = atomicAdd(&g_cursor[dst], 1);
    float2 rec;
    rec.x = __int_as_float(src);
    rec.y = g_dinv[src] * g_dinv[dst];
    g_csr[pos] = rec;
}

// ---------------------------------------------------------------------------
// hx = x @ W1  (N x 256  @  256 x 32), register-tiled.
__global__ void __launch_bounds__(256) gemm1_kernel(
        const float* __restrict__ x, const float* __restrict__ W1, int n) {
    __shared__ float xs[GROWS * (KT + 1)];   // stride 33
    __shared__ float Wts[KT * F1];           // 32 x 32

    int tid = threadIdx.x;
    int cg = tid & 3;
    int rg = tid >> 2;
    int row0 = blockIdx.x * GROWS;

    float acc[4][8];
#pragma unroll
    for (int i = 0; i < 4; i++)
#pragma unroll
        for (int j = 0; j < 8; j++) acc[i][j] = 0.0f;

    for (int kt = 0; kt < F0; kt += KT) {
        __syncthreads();
        {
            float4 w = *reinterpret_cast<const float4*>(W1 + (size_t)kt * F1 + tid * 4);
            *reinterpret_cast<float4*>(&Wts[tid * 4]) = w;
        }
#pragma unroll
        for (int it = 0; it < 8; it++) {
            int i = tid + it * 256;
            int r = i >> 3;
            int q = i & 7;
            int grow = row0 + r;
            float4 v = make_float4(0.f, 0.f, 0.f, 0.f);
            if (grow < n)
                v = *reinterpret_cast<const float4*>(x + (size_t)grow * F0 + kt + q * 4);
            float* dst = &xs[r * (KT + 1) + q * 4];
            dst[0] = v.x; dst[1] = v.y; dst[2] = v.z; dst[3] = v.w;
        }
        __syncthreads();

#pragma unroll
        for (int k = 0; k < KT; k++) {
            float xv[4];
#pragma unroll
            for (int i = 0; i < 4; i++)
                xv[i] = xs[(rg * 4 + i) * (KT + 1) + k];
            float4 w0 = *reinterpret_cast<const float4*>(&Wts[k * F1 + cg * 8]);
            float4 w1 = *reinterpret_cast<const float4*>(&Wts[k * F1 + cg * 8 + 4]);
#pragma unroll
            for (int i = 0; i < 4; i++) {
                acc[i][0] = fmaf(xv[i], w0.x, acc[i][0]);
                acc[i][1] = fmaf(xv[i], w0.y, acc[i][1]);
                acc[i][2] = fmaf(xv[i], w0.z, acc[i][2]);
                acc[i][3] = fmaf(xv[i], w0.w, acc[i][3]);
                acc[i][4] = fmaf(xv[i], w1.x, acc[i][4]);
                acc[i][5] = fmaf(xv[i], w1.y, acc[i][5]);
                acc[i][6] = fmaf(xv[i], w1.z, acc[i][6]);
                acc[i][7] = fmaf(xv[i], w1.w, acc[i][7]);
            }
        }
    }

#pragma unroll
    for (int i = 0; i < 4; i++) {
        int row = row0 + rg * 4 + i;
        if (row < n) {
            float4 o0 = make_float4(acc[i][0], acc[i][1], acc[i][2], acc[i][3]);
            float4 o1 = make_float4(acc[i][4], acc[i][5], acc[i][6], acc[i][7]);
            float* dst = &g_hx[(size_t)row * F1 + cg * 8];
            *reinterpret_cast<float4*>(dst)     = o0;
            *reinterpret_cast<float4*>(dst + 4) = o1;
        }
    }
}

// ---------------------------------------------------------------------------
// Gather layer 1: one warp per node, lane = feature col.
// h[node] = relu( sum_e w_e * hx[src_e] + dinv^2 * hx[node] + b1 )
__global__ void __launch_bounds__(256) gather1_kernel(
        const float* __restrict__ b1, int n) {
    int warp = (blockIdx.x * blockDim.x + threadIdx.x) >> 5;
    int lane = threadIdx.x & 31;
    if (warp >= n) return;
    int beg = g_off[warp];
    int end = g_off[warp + 1];
    float acc0 = 0.f, acc1 = 0.f;
    int k = beg;
    for (; k + 32 <= end; k += 32) {
        float2 rec = g_csr[k + lane];
        int   src = __float_as_int(rec.x);
        float w   = rec.y;
#pragma unroll
        for (int j = 0; j < 32; j += 2) {
            int   s0 = __shfl_sync(0xffffffffu, src, j);
            float w0 = __shfl_sync(0xffffffffu, w,   j);
            int   s1 = __shfl_sync(0xffffffffu, src, j + 1);
            float w1 = __shfl_sync(0xffffffffu, w,   j + 1);
            acc0 = fmaf(g_hx[(size_t)s0 * F1 + lane], w0, acc0);
            acc1 = fmaf(g_hx[(size_t)s1 * F1 + lane], w1, acc1);
        }
    }
    int rem = end - k;
    if (rem > 0) {
        float2 rec = make_float2(__int_as_float(0), 0.f);
        if (lane < rem) rec = g_csr[k + lane];
        int   src = __float_as_int(rec.x);
        float w   = rec.y;
        for (int j = 0; j < rem; j++) {
            int   s0 = __shfl_sync(0xffffffffu, src, j);
            float w0 = __shfl_sync(0xffffffffu, w,   j);
            acc0 = fmaf(g_hx[(size_t)s0 * F1 + lane], w0, acc0);
        }
    }
    float d = g_dinv[warp];
    float v = acc0 + acc1 + g_hx[(size_t)warp * F1 + lane] * d * d + b1[lane];
    g_h[(size_t)warp * F1 + lane] = v > 0.f ? v : 0.f;
}

// ---------------------------------------------------------------------------
// Gather layer 2 + fused epilogue: t = agg(h) + dinv^2*h ;
// mu = t@Wm + bm ; sigma = t@Wv + bv
__global__ void __launch_bounds__(256) gather2_kernel(
        const float* __restrict__ Wm, const float* __restrict__ bm,
        const float* __restrict__ Wv, const float* __restrict__ bv,
        float* __restrict__ out, int n) {
    __shared__ float Wms[F1 * F2];
    __shared__ float Wvs[F1 * F2];
    __shared__ float ts[8][F1];
    for (int i = threadIdx.x; i < F1 * F2; i += blockDim.x) {
        Wms[i] = Wm[i];
        Wvs[i] = Wv[i];
    }
    __syncthreads();

    int wIn  = threadIdx.x >> 5;
    int lane = threadIdx.x & 31;
    int node = blockIdx.x * 8 + wIn;
    if (node >= n) return;

    int beg = g_off[node];
    int end = g_off[node + 1];
    float acc0 = 0.f, acc1 = 0.f;
    int k = beg;
    for (; k + 32 <= end; k += 32) {
        float2 rec = g_csr[k + lane];
        int   src = __float_as_int(rec.x);
        float w   = rec.y;
#pragma unroll
        for (int j = 0; j < 32; j += 2) {
            int   s0 = __shfl_sync(0xffffffffu, src, j);
            float w0 = __shfl_sync(0xffffffffu, w,   j);
            int   s1 = __shfl_sync(0xffffffffu, src, j + 1);
            float w1 = __shfl_sync(0xffffffffu, w,   j + 1);
            acc0 = fmaf(g_h[(size_t)s0 * F1 + lane], w0, acc0);
            acc1 = fmaf(g_h[(size_t)s1 * F1 + lane], w1, acc1);
        }
    }
    int rem = end - k;
    if (rem > 0) {
        float2 rec = make_float2(__int_as_float(0), 0.f);
        if (lane < rem) rec = g_csr[k + lane];
        int   src = __float_as_int(rec.x);
        float w   = rec.y;
        for (int j = 0; j < rem; j++) {
            int   s0 = __shfl_sync(0xffffffffu, src, j);
            float w0 = __shfl_sync(0xffffffffu, w,   j);
            acc0 = fmaf(g_h[(size_t)s0 * F1 + lane], w0, acc0);
        }
    }
    float d = g_dinv[node];
    ts[wIn][lane] = acc0 + acc1 + g_h[(size_t)node * F1 + lane] * d * d;
    __syncwarp();

    // epilogue: lanes 0..15 -> mu cols, lanes 16..31 -> sigma cols
    int c = lane & 15;
    const float* Wp = (lane < 16) ? Wms : Wvs;
    float a = 0.f;
#pragma unroll
    for (int kk = 0; kk < F1; kk++)
        a = fmaf(ts[wIn][kk], Wp[kk * F2 + c], a);
    a += (lane < 16) ? bm[c] : bv[c];
    size_t o = (lane < 16) ? ((size_t)node * F2 + c)
                           : ((size_t)n * F2 + (size_t)node * F2 + c);
    out[o] = a;
}

// ---------------------------------------------------------------------------
extern "C" void kernel_launch(void* const* d_in, const int* in_sizes, int n_in,
                              void* d_out, int out_size) {
    const float* x  = (const float*)d_in[0];
    const int*   ei = (const int*)  d_in[1];
    const float* W1 = (const float*)d_in[2];
    const float* b1 = (const float*)d_in[3];
    const float* Wm = (const float*)d_in[4];
    const float* bm = (const float*)d_in[5];
    const float* Wv = (const float*)d_in[6];
    const float* bv = (const float*)d_in[7];
    float* out = (float*)d_out;

    int n = in_sizes[0] / F0;      // 100000
    int E = in_sizes[1] / 2;       // 3200000
    int nb = (n + SCAN_BLK - 1) / SCAN_BLK;

    zero_kernel<<<(n + 255) / 256, 256>>>(n);
    deg_kernel<<<(E + 255) / 256, 256>>>(ei, E);
    dinv_kernel<<<(n + 255) / 256, 256>>>(n);
    scan1_kernel<<<nb, SCAN_BLK>>>(n);
    scan2_kernel<<<1, 128>>>(nb);
    scan3_kernel<<<(n + 255) / 256, 256>>>(n, E);
    fill_kernel<<<(E + 255) / 256, 256>>>(ei, E);
    gemm1_kernel<<<(n + GROWS - 1) / GROWS, 256>>>(x, W1, n);
    gather1_kernel<<<(n * 32 + 255) / 256, 256>>>(b1, n);
    gather2_kernel<<<(n + 7) / 8, 256>>>(Wm, bm, Wv, bv, out, n);
}